// round 5
// baseline (speedup 1.0000x reference)
#include <cuda_runtime.h>
#include <cuda_fp16.h>
#include <cstdint>

// Problem constants (fixed by the dataset)
#define NN   100000       // nodes
#define NE   1600000      // edges (excluding self loops)
#define FD   128          // feature / hidden dim
#define NC   64           // classes
#define NB_SCAN 98        // ceil(NN / 1024), all blocks co-resident (<148 SMs)

// ---------------- scratch (device globals; no allocation allowed) ----------
__device__ __half g_bufh[NN * FD];  // GEMM output h (fp16, gather operand)
__device__ float  g_buf3[NN * FD];  // activation (agg+relu output, fp32)
__device__ float  g_dinv[NN];
__device__ int    g_deg[NN];        // in-degree (without self loop)
__device__ int    g_rowstart[NN];   // exclusive prefix of deg
__device__ int    g_cursor[NN];
__device__ int    g_csrc[NE];       // src node per incoming edge, grouped by dst
__device__ int    g_status[NB_SCAN];// lookback scan status (memset to 0)

// ---------------- preprocessing kernels ------------------------------------

__global__ void k_count(const int* __restrict__ ei)
{
    int e = blockIdx.x * blockDim.x + threadIdx.x;
    if (e < NE) {
        int d = ei[NE + e];
        atomicAdd(&g_deg[d], 1);
    }
}

// Single-pass scan over g_deg -> g_rowstart (exclusive), plus dinv.
// 98 blocks of 1024 threads, all resident simultaneously -> lookback is safe.
__global__ void __launch_bounds__(1024) k_scan()
{
    __shared__ int s[1024];
    __shared__ int sh_prefix;
    int t = threadIdx.x;
    int i = blockIdx.x * 1024 + t;
    int v = (i < NN) ? g_deg[i] : 0;
    s[t] = v;
    __syncthreads();
    #pragma unroll
    for (int off = 1; off < 1024; off <<= 1) {
        int add = (t >= off) ? s[t - off] : 0;
        __syncthreads();
        s[t] += add;
        __syncthreads();
    }
    // publish inclusive block total
    if (t == 1023) {
        int total = s[t];                       // < 2^30 always
        __threadfence();
        atomicExch(&g_status[blockIdx.x], total | 0x40000000);
    }
    // lookback: sum totals of all prior blocks
    if (t == 0) {
        int p = 0;
        for (int j = 0; j < (int)blockIdx.x; j++) {
            int st;
            do { st = atomicAdd(&g_status[j], 0); } while (!(st & 0x40000000));
            p += st & 0x3FFFFFFF;
        }
        sh_prefix = p;
    }
    __syncthreads();
    if (i < NN) {
        g_rowstart[i] = s[t] - v + sh_prefix;
        g_dinv[i] = rsqrtf((float)v + 1.0f);    // +1 = self loop
    }
}

__global__ void k_fill(const int* __restrict__ ei)
{
    int e = blockIdx.x * blockDim.x + threadIdx.x;
    if (e < NE) {
        int s = ei[e];
        int d = ei[NE + e];
        int p = g_rowstart[d] + atomicAdd(&g_cursor[d], 1);
        g_csrc[p] = s;
    }
}

// ---------------- TF32 helpers ---------------------------------------------
__device__ __forceinline__ uint32_t f2tf32(float v)
{
    uint32_t r;
    asm("cvt.rna.tf32.f32 %0, %1;" : "=r"(r) : "f"(v));
    return r;
}

__device__ __forceinline__ void mma_tf32(
    float& d0, float& d1, float& d2, float& d3,
    uint32_t a0, uint32_t a1, uint32_t a2, uint32_t a3,
    uint32_t b0, uint32_t b1)
{
    asm volatile(
        "mma.sync.aligned.m16n8k8.row.col.f32.tf32.tf32.f32 "
        "{%0,%1,%2,%3}, {%4,%5,%6,%7}, {%8,%9}, {%0,%1,%2,%3};"
        : "+f"(d0), "+f"(d1), "+f"(d2), "+f"(d3)
        : "r"(a0), "r"(a1), "r"(a2), "r"(a3), "r"(b0), "r"(b1));
}

// ---------------- GEMM: C[NN, OUT] = A[NN,128] @ W[OUT,128]^T (+bias) ------
// TF32 tensor-core GEMM with 2-term error-compensated split (lo*lo dropped).
// Block: 256 threads = 8 warps (4 m-warps x 2 n-warps).
// Block tile: 128 x OUT.  Warp tile: 32 x OUT/2 -> 2 m-atoms x OUT/16 n-atoms.
// HOUT: write C as __half (gather operand) instead of float.
template <int OUT, bool HOUT>
__global__ void __launch_bounds__(256) k_gemm(
    const float* __restrict__ A, const float* __restrict__ W,
    const float* __restrict__ bias, void* __restrict__ Cv)
{
    constexpr int NA = OUT / 16;          // n-atoms per warp (8 or 4)
    extern __shared__ float sm[];
    float* Xs = sm;                        // [128][132]
    float* Ws = sm + 128 * 132;            // [OUT][132]  Ws[j][k] = W[j][k]
    const int tid  = threadIdx.x;
    const int warp = tid >> 5;
    const int lane = tid & 31;

    for (int idx = tid; idx < OUT * 128; idx += 256) {
        int j = idx >> 7, k = idx & 127;
        Ws[j * 132 + k] = W[idx];
    }
    const int row0 = blockIdx.x * 128;
    for (int idx = tid; idx < 128 * 32; idx += 256) {
        int r = idx >> 5, c4 = idx & 31;
        float4 v = make_float4(0.f, 0.f, 0.f, 0.f);
        if (row0 + r < NN)
            v = reinterpret_cast<const float4*>(A)[(size_t)(row0 + r) * 32 + c4];
        *reinterpret_cast<float4*>(&Xs[r * 132 + c4 * 4]) = v;
    }
    __syncthreads();

    const int m_off = (warp >> 1) * 32;        // 0,32,64,96
    const int n_off = (warp & 1) * (OUT / 2);  // 0, OUT/2
    const int gid = lane >> 2;                 // group id 0..7
    const int tig = lane & 3;                  // thread in group 0..3

    float acc[2][NA][4];
    #pragma unroll
    for (int ma = 0; ma < 2; ma++)
        #pragma unroll
        for (int na = 0; na < NA; na++)
            #pragma unroll
            for (int c = 0; c < 4; c++) acc[ma][na][c] = 0.f;

    #pragma unroll 4
    for (int k0 = 0; k0 < 128; k0 += 8) {
        uint32_t ah[2][4], al[2][4];
        #pragma unroll
        for (int ma = 0; ma < 2; ma++) {
            int rbase = m_off + ma * 16 + gid;
            #pragma unroll
            for (int q = 0; q < 4; q++) {
                int r = rbase + ((q & 1) ? 8 : 0);
                int k = k0 + tig + ((q & 2) ? 4 : 0);
                float v  = Xs[r * 132 + k];
                uint32_t h = f2tf32(v);
                float lo = v - __uint_as_float(h);
                ah[ma][q] = h;
                al[ma][q] = f2tf32(lo);
            }
        }
        #pragma unroll
        for (int na = 0; na < NA; na++) {
            int n = n_off + na * 8 + gid;
            float v0 = Ws[n * 132 + k0 + tig];
            float v1 = Ws[n * 132 + k0 + tig + 4];
            uint32_t bh0 = f2tf32(v0), bh1 = f2tf32(v1);
            uint32_t bl0 = f2tf32(v0 - __uint_as_float(bh0));
            uint32_t bl1 = f2tf32(v1 - __uint_as_float(bh1));
            #pragma unroll
            for (int ma = 0; ma < 2; ma++) {
                float* d = acc[ma][na];
                mma_tf32(d[0], d[1], d[2], d[3],
                         al[ma][0], al[ma][1], al[ma][2], al[ma][3], bh0, bh1);
                mma_tf32(d[0], d[1], d[2], d[3],
                         ah[ma][0], ah[ma][1], ah[ma][2], ah[ma][3], bl0, bl1);
                mma_tf32(d[0], d[1], d[2], d[3],
                         ah[ma][0], ah[ma][1], ah[ma][2], ah[ma][3], bh0, bh1);
            }
        }
    }

    // epilogue
    #pragma unroll
    for (int ma = 0; ma < 2; ma++) {
        #pragma unroll
        for (int na = 0; na < NA; na++) {
            int col = n_off + na * 8 + 2 * tig;
            float bx = 0.f, by = 0.f;
            if (bias) { bx = __ldg(&bias[col]); by = __ldg(&bias[col + 1]); }
            int r0 = row0 + m_off + ma * 16 + gid;
            int r1 = r0 + 8;
            if (HOUT) {
                __half* C = (__half*)Cv;
                if (r0 < NN)
                    *reinterpret_cast<__half2*>(&C[(size_t)r0 * OUT + col]) =
                        __floats2half2_rn(acc[ma][na][0] + bx, acc[ma][na][1] + by);
                if (r1 < NN)
                    *reinterpret_cast<__half2*>(&C[(size_t)r1 * OUT + col]) =
                        __floats2half2_rn(acc[ma][na][2] + bx, acc[ma][na][3] + by);
            } else {
                float* C = (float*)Cv;
                if (r0 < NN)
                    *reinterpret_cast<float2*>(&C[(size_t)r0 * OUT + col]) =
                        make_float2(acc[ma][na][0] + bx, acc[ma][na][1] + by);
                if (r1 < NN)
                    *reinterpret_cast<float2*>(&C[(size_t)r1 * OUT + col]) =
                        make_float2(acc[ma][na][2] + bx, acc[ma][na][3] + by);
            }
        }
    }
}

// -------- aggregation + self-loop + bias + ReLU fused: warp per node -------
// h is fp16 (256B per node row): lane loads uint2 = 4 halves = dims 4*lane..+3
__global__ void k_agg_relu(const __half* __restrict__ h,
                           const float* __restrict__ bias,
                           float* __restrict__ out)
{
    int gw = (blockIdx.x * blockDim.x + threadIdx.x) >> 5;   // node id
    if (gw >= NN) return;
    int lane = threadIdx.x & 31;
    int beg = g_rowstart[gw];
    int cnt = g_deg[gw];
    float dinv_d = g_dinv[gw];
    const uint2* hp = reinterpret_cast<const uint2*>(h);
    float4 acc0 = make_float4(0.f, 0.f, 0.f, 0.f);
    float4 acc1 = make_float4(0.f, 0.f, 0.f, 0.f);
    int t = 0;
    for (; t + 1 < cnt; t += 2) {
        int   s0 = __ldg(&g_csrc[beg + t]);
        int   s1 = __ldg(&g_csrc[beg + t + 1]);
        float n0 = __ldg(&g_dinv[s0]) * dinv_d;
        float n1 = __ldg(&g_dinv[s1]) * dinv_d;
        uint2 u0 = __ldg(&hp[(size_t)s0 * 32 + lane]);
        uint2 u1 = __ldg(&hp[(size_t)s1 * 32 + lane]);
        float2 a0 = __half22float2(*reinterpret_cast<__half2*>(&u0.x));
        float2 b0 = __half22float2(*reinterpret_cast<__half2*>(&u0.y));
        float2 a1 = __half22float2(*reinterpret_cast<__half2*>(&u1.x));
        float2 b1 = __half22float2(*reinterpret_cast<__half2*>(&u1.y));
        acc0.x += n0 * a0.x; acc0.y += n0 * a0.y;
        acc0.z += n0 * b0.x; acc0.w += n0 * b0.y;
        acc1.x += n1 * a1.x; acc1.y += n1 * a1.y;
        acc1.z += n1 * b1.x; acc1.w += n1 * b1.y;
    }
    if (t < cnt) {
        int   s0 = __ldg(&g_csrc[beg + t]);
        float n0 = __ldg(&g_dinv[s0]) * dinv_d;
        uint2 u0 = __ldg(&hp[(size_t)s0 * 32 + lane]);
        float2 a0 = __half22float2(*reinterpret_cast<__half2*>(&u0.x));
        float2 b0 = __half22float2(*reinterpret_cast<__half2*>(&u0.y));
        acc0.x += n0 * a0.x; acc0.y += n0 * a0.y;
        acc0.z += n0 * b0.x; acc0.w += n0 * b0.y;
    }
    float c = dinv_d * dinv_d;                          // self-loop norm
    uint2 us = __ldg(&hp[(size_t)gw * 32 + lane]);
    float2 sa = __half22float2(*reinterpret_cast<__half2*>(&us.x));
    float2 sb = __half22float2(*reinterpret_cast<__half2*>(&us.y));
    float4 b  = __ldg(&reinterpret_cast<const float4*>(bias)[lane]);
    float4 r;
    r.x = fmaxf(acc0.x + acc1.x + c * sa.x + b.x, 0.f);
    r.y = fmaxf(acc0.y + acc1.y + c * sa.y + b.y, 0.f);
    r.z = fmaxf(acc0.z + acc1.z + c * sb.x + b.z, 0.f);
    r.w = fmaxf(acc0.w + acc1.w + c * sb.y + b.w, 0.f);
    reinterpret_cast<float4*>(out)[(size_t)gw * 32 + lane] = r;
}

// ---------------- launcher --------------------------------------------------
extern "C" void kernel_launch(void* const* d_in, const int* in_sizes, int n_in,
                              void* d_out, int out_size)
{
    (void)in_sizes; (void)n_in; (void)out_size;
    const float* x  = (const float*)d_in[0];
    const int*   ei = (const int*)d_in[1];          // int32 (JAX x64 disabled)
    const float* W1 = (const float*)d_in[2];
    const float* b1 = (const float*)d_in[3];
    const float* W2 = (const float*)d_in[4];
    const float* b2 = (const float*)d_in[5];
    const float* Wl = (const float*)d_in[6];
    const float* bl = (const float*)d_in[7];
    float* out = (float*)d_out;

    void *pbh, *pb3, *pdeg, *pcur, *pst;
    cudaGetSymbolAddress(&pbh, g_bufh);
    cudaGetSymbolAddress(&pb3, g_buf3);
    cudaGetSymbolAddress(&pdeg, g_deg);
    cudaGetSymbolAddress(&pcur, g_cursor);
    cudaGetSymbolAddress(&pst,  g_status);
    __half* bufh = (__half*)pbh;
    float*  buf3 = (float*)pb3;

    const int SMEM128 = (128 * 132 + 128 * 132) * 4;   // 135168 B
    const int SMEM64  = (128 * 132 + 64 * 132) * 4;    // 101376 B
    cudaFuncSetAttribute(k_gemm<128, true>,  cudaFuncAttributeMaxDynamicSharedMemorySize, SMEM128);
    cudaFuncSetAttribute(k_gemm<64, false>,  cudaFuncAttributeMaxDynamicSharedMemorySize, SMEM64);

    const int TB = 256;
    const int GB_E  = (NE + TB - 1) / TB;          // 6250
    const int GB_W  = (NN * 32 + TB - 1) / TB;     // 12500 (warp per node)
    const int GB_MM = (NN + 127) / 128;            // 782

    // --- zero-init via memset nodes (not kernel launches) ---
    cudaMemsetAsync(pdeg, 0, NN * sizeof(int));
    cudaMemsetAsync(pcur, 0, NN * sizeof(int));
    cudaMemsetAsync(pst,  0, NB_SCAN * sizeof(int));

    // --- graph preprocessing (3 kernel launches) ---
    k_count<<<GB_E, TB>>>(ei);
    k_scan<<<NB_SCAN, 1024>>>();
    k_fill<<<GB_E, TB>>>(ei);

    // --- layer 1 ---
    k_gemm<128, true><<<GB_MM, TB, SMEM128>>>(x, W1, nullptr, bufh);
    k_agg_relu<<<GB_W, TB>>>(bufh, b1, buf3);

    // --- layer 2 ---
    k_gemm<128, true><<<GB_MM, TB, SMEM128>>>(buf3, W2, nullptr, bufh);
    k_agg_relu<<<GB_W, TB>>>(bufh, b2, buf3);

    // --- readout ---
    k_gemm<64, false><<<GB_MM, TB, SMEM64>>>(buf3, Wl, bl, out);
}

// round 7
// speedup vs baseline: 1.5336x; 1.5336x over previous
#include <cuda_runtime.h>
#include <cuda_fp16.h>
#include <cstdint>

// Problem constants (fixed by the dataset)
#define NN   100000       // nodes
#define NE   1600000      // edges (excluding self loops)
#define FD   128          // feature / hidden dim
#define NC   64           // classes
#define NB_SCAN 98        // ceil(NN / 1024), all blocks co-resident (<148 SMs)

// ---------------- scratch (device globals; no allocation allowed) ----------
__device__ __half g_bufh[NN * FD];  // GEMM output h (fp16, gather operand)
__device__ float  g_buf3[NN * FD];  // activation (agg+relu output, fp32)
__device__ float  g_dinv[NN];
__device__ int    g_deg[NN];        // in-degree (without self loop)
__device__ int    g_rowstart[NN];   // exclusive prefix of deg
__device__ int    g_cursor[NN];
__device__ int    g_csrc[NE];       // src node per incoming edge, grouped by dst
__device__ int    g_status[NB_SCAN];// lookback scan status (memset to 0)

// ---------------- preprocessing kernels ------------------------------------

__global__ void k_count(const int* __restrict__ ei)
{
    int e = blockIdx.x * blockDim.x + threadIdx.x;
    if (e < NE) {
        int d = ei[NE + e];
        atomicAdd(&g_deg[d], 1);
    }
}

// Single-pass scan over g_deg -> g_rowstart (exclusive), plus dinv.
// 98 blocks of 1024 threads, all resident simultaneously -> lookback is safe.
__global__ void __launch_bounds__(1024) k_scan()
{
    __shared__ int s[1024];
    __shared__ int sh_prefix;
    int t = threadIdx.x;
    int i = blockIdx.x * 1024 + t;
    int v = (i < NN) ? g_deg[i] : 0;
    s[t] = v;
    __syncthreads();
    #pragma unroll
    for (int off = 1; off < 1024; off <<= 1) {
        int add = (t >= off) ? s[t - off] : 0;
        __syncthreads();
        s[t] += add;
        __syncthreads();
    }
    if (t == 1023) {
        int total = s[t];                       // < 2^30 always
        __threadfence();
        atomicExch(&g_status[blockIdx.x], total | 0x40000000);
    }
    if (t == 0) {
        int p = 0;
        for (int j = 0; j < (int)blockIdx.x; j++) {
            int st;
            do { st = atomicAdd(&g_status[j], 0); } while (!(st & 0x40000000));
            p += st & 0x3FFFFFFF;
        }
        sh_prefix = p;
    }
    __syncthreads();
    if (i < NN) {
        g_rowstart[i] = s[t] - v + sh_prefix;
        g_dinv[i] = rsqrtf((float)v + 1.0f);    // +1 = self loop
    }
}

__global__ void k_fill(const int* __restrict__ ei)
{
    int e = blockIdx.x * blockDim.x + threadIdx.x;
    if (e < NE) {
        int s = ei[e];
        int d = ei[NE + e];
        int p = g_rowstart[d] + atomicAdd(&g_cursor[d], 1);
        g_csrc[p] = s;
    }
}

// ---------------- fp16 MMA helper ------------------------------------------
__device__ __forceinline__ void mma_f16(
    float& d0, float& d1, float& d2, float& d3,
    uint32_t a0, uint32_t a1, uint32_t a2, uint32_t a3,
    uint32_t b0, uint32_t b1)
{
    asm volatile(
        "mma.sync.aligned.m16n8k16.row.col.f32.f16.f16.f32 "
        "{%0,%1,%2,%3}, {%4,%5,%6,%7}, {%8,%9}, {%0,%1,%2,%3};"
        : "+f"(d0), "+f"(d1), "+f"(d2), "+f"(d3)
        : "r"(a0), "r"(a1), "r"(a2), "r"(a3), "r"(b0), "r"(b1));
}

__device__ __forceinline__ uint32_t pack_h2(float x, float y)
{
    __half2 h = __floats2half2_rn(x, y);
    return *reinterpret_cast<uint32_t*>(&h);
}

// ---------------- GEMM: C[NN, OUT] = A[NN,128] @ W[OUT,128]^T (+bias) ------
// fp16 tensor-core GEMM (m16n8k16), fp32 accumulate. Inputs converted to fp16
// ONCE at smem-fill time. Block: 256 threads = 8 warps (4 m x 2 n).
// Block tile 128 x OUT; warp tile 32 x OUT/2 -> 2 m-atoms x OUT/16 n-atoms.
// smem row stride: 68 half2-words (64 data + 4 pad) -> conflict-free LDS.
// HOUT: write C as __half (gather operand) instead of float.
template <int OUT, bool HOUT>
__global__ void __launch_bounds__(256, 2) k_gemm(
    const float* __restrict__ A, const float* __restrict__ W,
    const float* __restrict__ bias, void* __restrict__ Cv)
{
    constexpr int NA = OUT / 16;          // n-atoms per warp (8 or 4)
    extern __shared__ uint32_t sm[];      // half2 units
    uint32_t* Xs = sm;                    // [128][68]
    uint32_t* Ws = sm + 128 * 68;         // [OUT][68]   Ws[j][k2] = W[j][2k..2k+1]
    const int tid  = threadIdx.x;
    const int warp = tid >> 5;
    const int lane = tid & 31;

    // load + convert W tile (OUT*32 float4s)
    for (int idx = tid; idx < OUT * 32; idx += 256) {
        int j = idx >> 5, c4 = idx & 31;
        float4 v = reinterpret_cast<const float4*>(W)[idx];
        uint2 p;
        p.x = pack_h2(v.x, v.y);
        p.y = pack_h2(v.z, v.w);
        *reinterpret_cast<uint2*>(&Ws[j * 68 + c4 * 2]) = p;
    }
    // load + convert A tile (guarded)
    const int row0 = blockIdx.x * 128;
    for (int idx = tid; idx < 128 * 32; idx += 256) {
        int r = idx >> 5, c4 = idx & 31;
        float4 v = make_float4(0.f, 0.f, 0.f, 0.f);
        if (row0 + r < NN)
            v = reinterpret_cast<const float4*>(A)[(size_t)(row0 + r) * 32 + c4];
        uint2 p;
        p.x = pack_h2(v.x, v.y);
        p.y = pack_h2(v.z, v.w);
        *reinterpret_cast<uint2*>(&Xs[r * 68 + c4 * 2]) = p;
    }
    __syncthreads();

    const int m_off = (warp >> 1) * 32;        // 0,32,64,96
    const int n_off = (warp & 1) * (OUT / 2);  // 0, OUT/2
    const int gid = lane >> 2;                 // group id 0..7
    const int tig = lane & 3;                  // thread in group 0..3

    float acc[2][NA][4];
    #pragma unroll
    for (int ma = 0; ma < 2; ma++)
        #pragma unroll
        for (int na = 0; na < NA; na++)
            #pragma unroll
            for (int c = 0; c < 4; c++) acc[ma][na][c] = 0.f;

    #pragma unroll
    for (int ks = 0; ks < 8; ks++) {           // k0 = ks*16, half2 base ks*8
        uint32_t a[2][4];
        #pragma unroll
        for (int ma = 0; ma < 2; ma++) {
            int row = m_off + ma * 16 + gid;
            a[ma][0] = Xs[row * 68 + ks * 8 + tig];
            a[ma][1] = Xs[(row + 8) * 68 + ks * 8 + tig];
            a[ma][2] = Xs[row * 68 + ks * 8 + tig + 4];
            a[ma][3] = Xs[(row + 8) * 68 + ks * 8 + tig + 4];
        }
        #pragma unroll
        for (int na = 0; na < NA; na++) {
            int n = n_off + na * 8 + gid;
            uint32_t b0 = Ws[n * 68 + ks * 8 + tig];
            uint32_t b1 = Ws[n * 68 + ks * 8 + tig + 4];
            #pragma unroll
            for (int ma = 0; ma < 2; ma++) {
                float* d = acc[ma][na];
                mma_f16(d[0], d[1], d[2], d[3],
                        a[ma][0], a[ma][1], a[ma][2], a[ma][3], b0, b1);
            }
        }
    }

    // epilogue
    #pragma unroll
    for (int ma = 0; ma < 2; ma++) {
        #pragma unroll
        for (int na = 0; na < NA; na++) {
            int col = n_off + na * 8 + 2 * tig;
            float bx = 0.f, by = 0.f;
            if (bias) { bx = __ldg(&bias[col]); by = __ldg(&bias[col + 1]); }
            int r0 = row0 + m_off + ma * 16 + gid;
            int r1 = r0 + 8;
            if (HOUT) {
                __half* C = (__half*)Cv;
                if (r0 < NN)
                    *reinterpret_cast<__half2*>(&C[(size_t)r0 * OUT + col]) =
                        __floats2half2_rn(acc[ma][na][0] + bx, acc[ma][na][1] + by);
                if (r1 < NN)
                    *reinterpret_cast<__half2*>(&C[(size_t)r1 * OUT + col]) =
                        __floats2half2_rn(acc[ma][na][2] + bx, acc[ma][na][3] + by);
            } else {
                float* C = (float*)Cv;
                if (r0 < NN)
                    *reinterpret_cast<float2*>(&C[(size_t)r0 * OUT + col]) =
                        make_float2(acc[ma][na][0] + bx, acc[ma][na][1] + by);
                if (r1 < NN)
                    *reinterpret_cast<float2*>(&C[(size_t)r1 * OUT + col]) =
                        make_float2(acc[ma][na][2] + bx, acc[ma][na][3] + by);
            }
        }
    }
}

// -------- aggregation + self-loop + bias + ReLU fused: warp per node -------
// h is fp16 (256B per node row): lane loads uint2 = 4 halves = dims 4*lane..+3
__global__ void k_agg_relu(const __half* __restrict__ h,
                           const float* __restrict__ bias,
                           float* __restrict__ out)
{
    int gw = (blockIdx.x * blockDim.x + threadIdx.x) >> 5;   // node id
    if (gw >= NN) return;
    int lane = threadIdx.x & 31;
    int beg = g_rowstart[gw];
    int cnt = g_deg[gw];
    float dinv_d = g_dinv[gw];
    const uint2* hp = reinterpret_cast<const uint2*>(h);
    float4 acc0 = make_float4(0.f, 0.f, 0.f, 0.f);
    float4 acc1 = make_float4(0.f, 0.f, 0.f, 0.f);
    int t = 0;
    for (; t + 1 < cnt; t += 2) {
        int   s0 = __ldg(&g_csrc[beg + t]);
        int   s1 = __ldg(&g_csrc[beg + t + 1]);
        float n0 = __ldg(&g_dinv[s0]) * dinv_d;
        float n1 = __ldg(&g_dinv[s1]) * dinv_d;
        uint2 u0 = __ldg(&hp[(size_t)s0 * 32 + lane]);
        uint2 u1 = __ldg(&hp[(size_t)s1 * 32 + lane]);
        float2 a0 = __half22float2(*reinterpret_cast<__half2*>(&u0.x));
        float2 b0 = __half22float2(*reinterpret_cast<__half2*>(&u0.y));
        float2 a1 = __half22float2(*reinterpret_cast<__half2*>(&u1.x));
        float2 b1 = __half22float2(*reinterpret_cast<__half2*>(&u1.y));
        acc0.x += n0 * a0.x; acc0.y += n0 * a0.y;
        acc0.z += n0 * b0.x; acc0.w += n0 * b0.y;
        acc1.x += n1 * a1.x; acc1.y += n1 * a1.y;
        acc1.z += n1 * b1.x; acc1.w += n1 * b1.y;
    }
    if (t < cnt) {
        int   s0 = __ldg(&g_csrc[beg + t]);
        float n0 = __ldg(&g_dinv[s0]) * dinv_d;
        uint2 u0 = __ldg(&hp[(size_t)s0 * 32 + lane]);
        float2 a0 = __half22float2(*reinterpret_cast<__half2*>(&u0.x));
        float2 b0 = __half22float2(*reinterpret_cast<__half2*>(&u0.y));
        acc0.x += n0 * a0.x; acc0.y += n0 * a0.y;
        acc0.z += n0 * b0.x; acc0.w += n0 * b0.y;
    }
    float c = dinv_d * dinv_d;                          // self-loop norm
    uint2 us = __ldg(&hp[(size_t)gw * 32 + lane]);
    float2 sa = __half22float2(*reinterpret_cast<__half2*>(&us.x));
    float2 sb = __half22float2(*reinterpret_cast<__half2*>(&us.y));
    float4 b  = __ldg(&reinterpret_cast<const float4*>(bias)[lane]);
    float4 r;
    r.x = fmaxf(acc0.x + acc1.x + c * sa.x + b.x, 0.f);
    r.y = fmaxf(acc0.y + acc1.y + c * sa.y + b.y, 0.f);
    r.z = fmaxf(acc0.z + acc1.z + c * sb.x + b.z, 0.f);
    r.w = fmaxf(acc0.w + acc1.w + c * sb.y + b.w, 0.f);
    reinterpret_cast<float4*>(out)[(size_t)gw * 32 + lane] = r;
}

// ---------------- launcher --------------------------------------------------
extern "C" void kernel_launch(void* const* d_in, const int* in_sizes, int n_in,
                              void* d_out, int out_size)
{
    (void)in_sizes; (void)n_in; (void)out_size;
    const float* x  = (const float*)d_in[0];
    const int*   ei = (const int*)d_in[1];          // int32 (JAX x64 disabled)
    const float* W1 = (const float*)d_in[2];
    const float* b1 = (const float*)d_in[3];
    const float* W2 = (const float*)d_in[4];
    const float* b2 = (const float*)d_in[5];
    const float* Wl = (const float*)d_in[6];
    const float* bl = (const float*)d_in[7];
    float* out = (float*)d_out;

    void *pbh, *pb3, *pdeg, *pcur, *pst;
    cudaGetSymbolAddress(&pbh, g_bufh);
    cudaGetSymbolAddress(&pb3, g_buf3);
    cudaGetSymbolAddress(&pdeg, g_deg);
    cudaGetSymbolAddress(&pcur, g_cursor);
    cudaGetSymbolAddress(&pst,  g_status);
    __half* bufh = (__half*)pbh;
    float*  buf3 = (float*)pb3;

    const int SMEM128 = (128 * 68 + 128 * 68) * 4;   // 69632 B
    const int SMEM64  = (128 * 68 + 64 * 68) * 4;    // 52224 B
    cudaFuncSetAttribute(k_gemm<128, true>,  cudaFuncAttributeMaxDynamicSharedMemorySize, SMEM128);
    cudaFuncSetAttribute(k_gemm<64, false>,  cudaFuncAttributeMaxDynamicSharedMemorySize, SMEM64);

    const int TB = 256;
    const int GB_E  = (NE + TB - 1) / TB;          // 6250
    const int GB_W  = (NN * 32 + TB - 1) / TB;     // 12500 (warp per node)
    const int GB_MM = (NN + 127) / 128;            // 782

    // --- zero-init via memset nodes (not kernel launches) ---
    cudaMemsetAsync(pdeg, 0, NN * sizeof(int));
    cudaMemsetAsync(pcur, 0, NN * sizeof(int));
    cudaMemsetAsync(pst,  0, NB_SCAN * sizeof(int));

    // --- graph preprocessing (3 kernel launches) ---
    k_count<<<GB_E, TB>>>(ei);
    k_scan<<<NB_SCAN, 1024>>>();
    k_fill<<<GB_E, TB>>>(ei);

    // --- layer 1 ---
    k_gemm<128, true><<<GB_MM, TB, SMEM128>>>(x, W1, nullptr, bufh);
    k_agg_relu<<<GB_W, TB>>>(bufh, b1, buf3);

    // --- layer 2 ---
    k_gemm<128, true><<<GB_MM, TB, SMEM128>>>(buf3, W2, nullptr, bufh);
    k_agg_relu<<<GB_W, TB>>>(bufh, b2, buf3);

    // --- readout ---
    k_gemm<64, false><<<GB_MM, TB, SMEM64>>>(buf3, Wl, bl, out);
}

// round 8
// speedup vs baseline: 1.6873x; 1.1002x over previous
#include <cuda_runtime.h>
#include <cuda_fp16.h>
#include <cstdint>

// Problem constants (fixed by the dataset)
#define NN   100000       // nodes
#define NE   1600000      // edges (excluding self loops)
#define FD   128          // feature / hidden dim
#define NC   64           // classes
#define NB_SCAN 98        // ceil(NN / 1024), all blocks co-resident (<148 SMs)

// ---------------- scratch (device globals; no allocation allowed) ----------
__device__ __half g_bufh[NN * FD];   // GEMM output h (fp16, gather operand)
__device__ __half g_bufact[NN * FD]; // agg+relu output (fp16, GEMM input)
__device__ float  g_dinv[NN];
__device__ int    g_deg[NN];         // in-degree (without self loop)
__device__ int    g_rowstart[NN];    // exclusive prefix of deg
__device__ int    g_cursor[NN];
__device__ int2   g_pair[NE];        // (src, norm-bits) per edge, grouped by dst
__device__ int    g_status[NB_SCAN]; // lookback scan status (memset to 0)

// ---------------- preprocessing kernels ------------------------------------

__global__ void k_count(const int* __restrict__ ei)
{
    int e = blockIdx.x * blockDim.x + threadIdx.x;
    if (e < NE) {
        int d = ei[NE + e];
        atomicAdd(&g_deg[d], 1);
    }
}

// Single-pass scan over g_deg -> g_rowstart (exclusive), plus dinv.
// 98 blocks of 1024 threads, all resident simultaneously -> lookback is safe.
__global__ void __launch_bounds__(1024) k_scan()
{
    __shared__ int s[1024];
    __shared__ int sh_prefix;
    int t = threadIdx.x;
    int i = blockIdx.x * 1024 + t;
    int v = (i < NN) ? g_deg[i] : 0;
    s[t] = v;
    __syncthreads();
    #pragma unroll
    for (int off = 1; off < 1024; off <<= 1) {
        int add = (t >= off) ? s[t - off] : 0;
        __syncthreads();
        s[t] += add;
        __syncthreads();
    }
    if (t == 1023) {
        int total = s[t];                       // < 2^30 always
        __threadfence();
        atomicExch(&g_status[blockIdx.x], total | 0x40000000);
    }
    if (t == 0) {
        int p = 0;
        for (int j = 0; j < (int)blockIdx.x; j++) {
            int st;
            do { st = atomicAdd(&g_status[j], 0); } while (!(st & 0x40000000));
            p += st & 0x3FFFFFFF;
        }
        sh_prefix = p;
    }
    __syncthreads();
    if (i < NN) {
        g_rowstart[i] = s[t] - v + sh_prefix;
        g_dinv[i] = rsqrtf((float)v + 1.0f);    // +1 = self loop
    }
}

__global__ void k_fill(const int* __restrict__ ei)
{
    int e = blockIdx.x * blockDim.x + threadIdx.x;
    if (e < NE) {
        int s = ei[e];
        int d = ei[NE + e];
        int p = g_rowstart[d] + atomicAdd(&g_cursor[d], 1);
        float nm = __ldg(&g_dinv[s]) * __ldg(&g_dinv[d]);
        g_pair[p] = make_int2(s, __float_as_int(nm));
    }
}

// ---------------- fp16 MMA helper ------------------------------------------
__device__ __forceinline__ void mma_f16(
    float& d0, float& d1, float& d2, float& d3,
    uint32_t a0, uint32_t a1, uint32_t a2, uint32_t a3,
    uint32_t b0, uint32_t b1)
{
    asm volatile(
        "mma.sync.aligned.m16n8k16.row.col.f32.f16.f16.f32 "
        "{%0,%1,%2,%3}, {%4,%5,%6,%7}, {%8,%9}, {%0,%1,%2,%3};"
        : "+f"(d0), "+f"(d1), "+f"(d2), "+f"(d3)
        : "r"(a0), "r"(a1), "r"(a2), "r"(a3), "r"(b0), "r"(b1));
}

__device__ __forceinline__ uint32_t pack_h2(float x, float y)
{
    __half2 h = __floats2half2_rn(x, y);
    return *reinterpret_cast<uint32_t*>(&h);
}

// ---------------- GEMM: C[NN, OUT] = A[NN,128] @ W[OUT,128]^T (+bias) ------
// fp16 tensor-core GEMM (m16n8k16), fp32 accumulate.
// HIN:  A is fp16 in global (no conversion at fill).  else fp32 -> cvt once.
// HOUT: write C as fp16 (gather operand), else fp32.
// Block: 256 threads = 8 warps (4 m x 2 n). Block tile 128 x OUT.
// smem row stride: 68 half2-words (64 data + 4 pad) -> conflict-free LDS.
template <int OUT, bool HIN, bool HOUT>
__global__ void __launch_bounds__(256, 2) k_gemm(
    const void* __restrict__ Av, const float* __restrict__ W,
    const float* __restrict__ bias, void* __restrict__ Cv)
{
    constexpr int NA = OUT / 16;          // n-atoms per warp (8 or 4)
    extern __shared__ uint32_t sm[];      // half2 units
    uint32_t* Xs = sm;                    // [128][68]
    uint32_t* Ws = sm + 128 * 68;         // [OUT][68]   Ws[j][k2] = W[j][2k..2k+1]
    const int tid  = threadIdx.x;
    const int warp = tid >> 5;
    const int lane = tid & 31;

    // load + convert W tile (OUT*32 float4s)
    for (int idx = tid; idx < OUT * 32; idx += 256) {
        int j = idx >> 5, c4 = idx & 31;
        float4 v = reinterpret_cast<const float4*>(W)[idx];
        uint2 p;
        p.x = pack_h2(v.x, v.y);
        p.y = pack_h2(v.z, v.w);
        *reinterpret_cast<uint2*>(&Ws[j * 68 + c4 * 2]) = p;
    }
    // load A tile (guarded)
    const int row0 = blockIdx.x * 128;
    if (HIN) {
        const uint4* hp = reinterpret_cast<const uint4*>(Av);   // 16 uint4/row
        for (int idx = tid; idx < 128 * 16; idx += 256) {
            int r = idx >> 4, c8 = idx & 15;
            uint4 v = make_uint4(0u, 0u, 0u, 0u);
            if (row0 + r < NN)
                v = __ldg(&hp[(size_t)(row0 + r) * 16 + c8]);
            *reinterpret_cast<uint4*>(&Xs[r * 68 + c8 * 4]) = v;
        }
    } else {
        const float4* fp = reinterpret_cast<const float4*>(Av);
        for (int idx = tid; idx < 128 * 32; idx += 256) {
            int r = idx >> 5, c4 = idx & 31;
            float4 v = make_float4(0.f, 0.f, 0.f, 0.f);
            if (row0 + r < NN)
                v = fp[(size_t)(row0 + r) * 32 + c4];
            uint2 p;
            p.x = pack_h2(v.x, v.y);
            p.y = pack_h2(v.z, v.w);
            *reinterpret_cast<uint2*>(&Xs[r * 68 + c4 * 2]) = p;
        }
    }
    __syncthreads();

    const int m_off = (warp >> 1) * 32;        // 0,32,64,96
    const int n_off = (warp & 1) * (OUT / 2);  // 0, OUT/2
    const int gid = lane >> 2;                 // group id 0..7
    const int tig = lane & 3;                  // thread in group 0..3

    float acc[2][NA][4];
    #pragma unroll
    for (int ma = 0; ma < 2; ma++)
        #pragma unroll
        for (int na = 0; na < NA; na++)
            #pragma unroll
            for (int c = 0; c < 4; c++) acc[ma][na][c] = 0.f;

    #pragma unroll
    for (int ks = 0; ks < 8; ks++) {           // k0 = ks*16, half2 base ks*8
        uint32_t a[2][4];
        #pragma unroll
        for (int ma = 0; ma < 2; ma++) {
            int row = m_off + ma * 16 + gid;
            a[ma][0] = Xs[row * 68 + ks * 8 + tig];
            a[ma][1] = Xs[(row + 8) * 68 + ks * 8 + tig];
            a[ma][2] = Xs[row * 68 + ks * 8 + tig + 4];
            a[ma][3] = Xs[(row + 8) * 68 + ks * 8 + tig + 4];
        }
        #pragma unroll
        for (int na = 0; na < NA; na++) {
            int n = n_off + na * 8 + gid;
            uint32_t b0 = Ws[n * 68 + ks * 8 + tig];
            uint32_t b1 = Ws[n * 68 + ks * 8 + tig + 4];
            #pragma unroll
            for (int ma = 0; ma < 2; ma++) {
                float* d = acc[ma][na];
                mma_f16(d[0], d[1], d[2], d[3],
                        a[ma][0], a[ma][1], a[ma][2], a[ma][3], b0, b1);
            }
        }
    }

    // epilogue
    #pragma unroll
    for (int ma = 0; ma < 2; ma++) {
        #pragma unroll
        for (int na = 0; na < NA; na++) {
            int col = n_off + na * 8 + 2 * tig;
            float bx = 0.f, by = 0.f;
            if (bias) { bx = __ldg(&bias[col]); by = __ldg(&bias[col + 1]); }
            int r0 = row0 + m_off + ma * 16 + gid;
            int r1 = r0 + 8;
            if (HOUT) {
                __half* C = (__half*)Cv;
                if (r0 < NN)
                    *reinterpret_cast<__half2*>(&C[(size_t)r0 * OUT + col]) =
                        __floats2half2_rn(acc[ma][na][0] + bx, acc[ma][na][1] + by);
                if (r1 < NN)
                    *reinterpret_cast<__half2*>(&C[(size_t)r1 * OUT + col]) =
                        __floats2half2_rn(acc[ma][na][2] + bx, acc[ma][na][3] + by);
            } else {
                float* C = (float*)Cv;
                if (r0 < NN)
                    *reinterpret_cast<float2*>(&C[(size_t)r0 * OUT + col]) =
                        make_float2(acc[ma][na][0] + bx, acc[ma][na][1] + by);
                if (r1 < NN)
                    *reinterpret_cast<float2*>(&C[(size_t)r1 * OUT + col]) =
                        make_float2(acc[ma][na][2] + bx, acc[ma][na][3] + by);
            }
        }
    }
}

// -------- aggregation + self-loop + bias + ReLU fused: warp per node -------
// h fp16 (256B rows). Warp batch-loads 32 (src, norm) pairs in ONE vector LDG,
// shfl-broadcasts them, inner loop unrolled x4 for gather MLP.
// Output written as fp16 (feeds next GEMM, which would round to fp16 anyway).
__global__ void k_agg_relu(const __half* __restrict__ h,
                           const float* __restrict__ bias,
                           __half* __restrict__ out)
{
    int gw = (blockIdx.x * blockDim.x + threadIdx.x) >> 5;   // node id
    if (gw >= NN) return;
    int lane = threadIdx.x & 31;
    int beg = g_rowstart[gw];
    int cnt = g_deg[gw];
    const uint2* hp = reinterpret_cast<const uint2*>(h);

    float4 acc0 = make_float4(0.f, 0.f, 0.f, 0.f);
    float4 acc1 = make_float4(0.f, 0.f, 0.f, 0.f);
    float4 acc2 = make_float4(0.f, 0.f, 0.f, 0.f);
    float4 acc3 = make_float4(0.f, 0.f, 0.f, 0.f);

    for (int t0 = 0; t0 < cnt; t0 += 32) {
        int2 pr = make_int2(0, 0);
        if (t0 + lane < cnt) pr = __ldg(&g_pair[beg + t0 + lane]);
        int m = min(32, cnt - t0);
        int j = 0;
        for (; j + 4 <= m; j += 4) {
            int   s0 = __shfl_sync(0xFFFFFFFFu, pr.x, j);
            int   s1 = __shfl_sync(0xFFFFFFFFu, pr.x, j + 1);
            int   s2 = __shfl_sync(0xFFFFFFFFu, pr.x, j + 2);
            int   s3 = __shfl_sync(0xFFFFFFFFu, pr.x, j + 3);
            float n0 = __int_as_float(__shfl_sync(0xFFFFFFFFu, pr.y, j));
            float n1 = __int_as_float(__shfl_sync(0xFFFFFFFFu, pr.y, j + 1));
            float n2 = __int_as_float(__shfl_sync(0xFFFFFFFFu, pr.y, j + 2));
            float n3 = __int_as_float(__shfl_sync(0xFFFFFFFFu, pr.y, j + 3));
            uint2 u0 = __ldg(&hp[(size_t)s0 * 32 + lane]);
            uint2 u1 = __ldg(&hp[(size_t)s1 * 32 + lane]);
            uint2 u2 = __ldg(&hp[(size_t)s2 * 32 + lane]);
            uint2 u3 = __ldg(&hp[(size_t)s3 * 32 + lane]);
            float2 p0a = __half22float2(*reinterpret_cast<__half2*>(&u0.x));
            float2 p0b = __half22float2(*reinterpret_cast<__half2*>(&u0.y));
            float2 p1a = __half22float2(*reinterpret_cast<__half2*>(&u1.x));
            float2 p1b = __half22float2(*reinterpret_cast<__half2*>(&u1.y));
            float2 p2a = __half22float2(*reinterpret_cast<__half2*>(&u2.x));
            float2 p2b = __half22float2(*reinterpret_cast<__half2*>(&u2.y));
            float2 p3a = __half22float2(*reinterpret_cast<__half2*>(&u3.x));
            float2 p3b = __half22float2(*reinterpret_cast<__half2*>(&u3.y));
            acc0.x += n0 * p0a.x; acc0.y += n0 * p0a.y;
            acc0.z += n0 * p0b.x; acc0.w += n0 * p0b.y;
            acc1.x += n1 * p1a.x; acc1.y += n1 * p1a.y;
            acc1.z += n1 * p1b.x; acc1.w += n1 * p1b.y;
            acc2.x += n2 * p2a.x; acc2.y += n2 * p2a.y;
            acc2.z += n2 * p2b.x; acc2.w += n2 * p2b.y;
            acc3.x += n3 * p3a.x; acc3.y += n3 * p3a.y;
            acc3.z += n3 * p3b.x; acc3.w += n3 * p3b.y;
        }
        for (; j < m; j++) {
            int   s0 = __shfl_sync(0xFFFFFFFFu, pr.x, j);
            float n0 = __int_as_float(__shfl_sync(0xFFFFFFFFu, pr.y, j));
            uint2 u0 = __ldg(&hp[(size_t)s0 * 32 + lane]);
            float2 p0a = __half22float2(*reinterpret_cast<__half2*>(&u0.x));
            float2 p0b = __half22float2(*reinterpret_cast<__half2*>(&u0.y));
            acc0.x += n0 * p0a.x; acc0.y += n0 * p0a.y;
            acc0.z += n0 * p0b.x; acc0.w += n0 * p0b.y;
        }
    }

    float dinv_d = g_dinv[gw];
    float c = dinv_d * dinv_d;                          // self-loop norm
    uint2 us = __ldg(&hp[(size_t)gw * 32 + lane]);
    float2 sa = __half22float2(*reinterpret_cast<__half2*>(&us.x));
    float2 sb = __half22float2(*reinterpret_cast<__half2*>(&us.y));
    float4 b  = __ldg(&reinterpret_cast<const float4*>(bias)[lane]);
    float rx = fmaxf(acc0.x + acc1.x + acc2.x + acc3.x + c * sa.x + b.x, 0.f);
    float ry = fmaxf(acc0.y + acc1.y + acc2.y + acc3.y + c * sa.y + b.y, 0.f);
    float rz = fmaxf(acc0.z + acc1.z + acc2.z + acc3.z + c * sb.x + b.z, 0.f);
    float rw = fmaxf(acc0.w + acc1.w + acc2.w + acc3.w + c * sb.y + b.w, 0.f);
    uint2 o;
    o.x = pack_h2(rx, ry);
    o.y = pack_h2(rz, rw);
    reinterpret_cast<uint2*>(out)[(size_t)gw * 32 + lane] = o;
}

// ---------------- launcher --------------------------------------------------
extern "C" void kernel_launch(void* const* d_in, const int* in_sizes, int n_in,
                              void* d_out, int out_size)
{
    (void)in_sizes; (void)n_in; (void)out_size;
    const float* x  = (const float*)d_in[0];
    const int*   ei = (const int*)d_in[1];          // int32 (JAX x64 disabled)
    const float* W1 = (const float*)d_in[2];
    const float* b1 = (const float*)d_in[3];
    const float* W2 = (const float*)d_in[4];
    const float* b2 = (const float*)d_in[5];
    const float* Wl = (const float*)d_in[6];
    const float* bl = (const float*)d_in[7];
    float* out = (float*)d_out;

    void *pbh, *pba, *pdeg, *pcur, *pst;
    cudaGetSymbolAddress(&pbh, g_bufh);
    cudaGetSymbolAddress(&pba, g_bufact);
    cudaGetSymbolAddress(&pdeg, g_deg);
    cudaGetSymbolAddress(&pcur, g_cursor);
    cudaGetSymbolAddress(&pst,  g_status);
    __half* bufh = (__half*)pbh;
    __half* bufact = (__half*)pba;

    const int SMEM128 = (128 * 68 + 128 * 68) * 4;   // 69632 B
    const int SMEM64  = (128 * 68 + 64 * 68) * 4;    // 52224 B
    cudaFuncSetAttribute((const void*)k_gemm<128, false, true>,
                         cudaFuncAttributeMaxDynamicSharedMemorySize, SMEM128);
    cudaFuncSetAttribute((const void*)k_gemm<128, true, true>,
                         cudaFuncAttributeMaxDynamicSharedMemorySize, SMEM128);
    cudaFuncSetAttribute((const void*)k_gemm<64, true, false>,
                         cudaFuncAttributeMaxDynamicSharedMemorySize, SMEM64);

    const int TB = 256;
    const int GB_E  = (NE + TB - 1) / TB;          // 6250
    const int GB_W  = (NN * 32 + TB - 1) / TB;     // 12500 (warp per node)
    const int GB_MM = (NN + 127) / 128;            // 782

    // --- zero-init via memset nodes (not kernel launches) ---
    cudaMemsetAsync(pdeg, 0, NN * sizeof(int));
    cudaMemsetAsync(pcur, 0, NN * sizeof(int));
    cudaMemsetAsync(pst,  0, NB_SCAN * sizeof(int));

    // --- graph preprocessing (3 kernel launches) ---
    k_count<<<GB_E, TB>>>(ei);
    k_scan<<<NB_SCAN, 1024>>>();
    k_fill<<<GB_E, TB>>>(ei);

    // --- layer 1 ---
    k_gemm<128, false, true><<<GB_MM, TB, SMEM128>>>(x, W1, nullptr, bufh);
    k_agg_relu<<<GB_W, TB>>>(bufh, b1, bufact);

    // --- layer 2 ---
    k_gemm<128, true, true><<<GB_MM, TB, SMEM128>>>(bufact, W2, nullptr, bufh);
    k_agg_relu<<<GB_W, TB>>>(bufh, b2, bufact);

    // --- readout ---
    k_gemm<64, true, false><<<GB_MM, TB, SMEM64>>>(bufact, Wl, bl, out);
}

// round 9
// speedup vs baseline: 1.7173x; 1.0178x over previous
#include <cuda_runtime.h>
#include <cuda_fp16.h>
#include <cstdint>

// Problem constants (fixed by the dataset)
#define NN   100000       // nodes
#define NE   1600000      // edges (excluding self loops)
#define FD   128          // feature / hidden dim
#define NC   64           // classes
#define NB_SCAN 98        // ceil(NN / 1024), all blocks co-resident (<148 SMs)
#define NTILES 782        // ceil(NN / 128)
#define GEMM_GRID 296     // 2 CTAs/SM * 148 SMs

// ---------------- scratch (device globals; no allocation allowed) ----------
__device__ __half g_xh[NN * FD];     // x converted to fp16 (GEMM-1 input)
__device__ __half g_bufh[NN * FD];   // GEMM output h (fp16, gather operand)
__device__ __half g_bufact[NN * FD]; // agg+relu output (fp16, GEMM input)
__device__ float  g_dinv[NN];
__device__ int    g_deg[NN];         // in-degree (without self loop)
__device__ int    g_rowstart[NN];    // exclusive prefix of deg
__device__ int    g_cursor[NN];
__device__ int2   g_pair[NE];        // (src, norm-bits) per edge, grouped by dst
__device__ int    g_status[NB_SCAN]; // lookback scan status (memset to 0)

// ---------------- preprocessing kernels ------------------------------------

__global__ void k_count(const int* __restrict__ ei)
{
    int e = blockIdx.x * blockDim.x + threadIdx.x;
    if (e < NE) {
        int d = ei[NE + e];
        atomicAdd(&g_deg[d], 1);
    }
}

// Single-pass scan over g_deg -> g_rowstart (exclusive), plus dinv.
// 98 blocks of 1024 threads, all resident simultaneously -> lookback is safe.
__global__ void __launch_bounds__(1024) k_scan()
{
    __shared__ int s[1024];
    __shared__ int sh_prefix;
    int t = threadIdx.x;
    int i = blockIdx.x * 1024 + t;
    int v = (i < NN) ? g_deg[i] : 0;
    s[t] = v;
    __syncthreads();
    #pragma unroll
    for (int off = 1; off < 1024; off <<= 1) {
        int add = (t >= off) ? s[t - off] : 0;
        __syncthreads();
        s[t] += add;
        __syncthreads();
    }
    if (t == 1023) {
        int total = s[t];                       // < 2^30 always
        __threadfence();
        atomicExch(&g_status[blockIdx.x], total | 0x40000000);
    }
    if (t == 0) {
        int p = 0;
        for (int j = 0; j < (int)blockIdx.x; j++) {
            int st;
            do { st = atomicAdd(&g_status[j], 0); } while (!(st & 0x40000000));
            p += st & 0x3FFFFFFF;
        }
        sh_prefix = p;
    }
    __syncthreads();
    if (i < NN) {
        g_rowstart[i] = s[t] - v + sh_prefix;
        g_dinv[i] = rsqrtf((float)v + 1.0f);    // +1 = self loop
    }
}

__global__ void k_fill(const int* __restrict__ ei)
{
    int e = blockIdx.x * blockDim.x + threadIdx.x;
    if (e < NE) {
        int s = ei[e];
        int d = ei[NE + e];
        int p = g_rowstart[d] + atomicAdd(&g_cursor[d], 1);
        float nm = __ldg(&g_dinv[s]) * __ldg(&g_dinv[d]);
        g_pair[p] = make_int2(s, __float_as_int(nm));
    }
}

// ---------------- helpers ---------------------------------------------------
__device__ __forceinline__ void mma_f16(
    float& d0, float& d1, float& d2, float& d3,
    uint32_t a0, uint32_t a1, uint32_t a2, uint32_t a3,
    uint32_t b0, uint32_t b1)
{
    asm volatile(
        "mma.sync.aligned.m16n8k16.row.col.f32.f16.f16.f32 "
        "{%0,%1,%2,%3}, {%4,%5,%6,%7}, {%8,%9}, {%0,%1,%2,%3};"
        : "+f"(d0), "+f"(d1), "+f"(d2), "+f"(d3)
        : "r"(a0), "r"(a1), "r"(a2), "r"(a3), "r"(b0), "r"(b1));
}

__device__ __forceinline__ uint32_t pack_h2(float x, float y)
{
    __half2 h = __floats2half2_rn(x, y);
    return *reinterpret_cast<uint32_t*>(&h);
}

// ---------------- x -> fp16 conversion (once) -------------------------------
__global__ void k_cvt(const float4* __restrict__ x, uint2* __restrict__ xh)
{
    int i = blockIdx.x * blockDim.x + threadIdx.x;   // over NN*32
    if (i < NN * 32) {
        float4 v = __ldg(&x[i]);
        uint2 p;
        p.x = pack_h2(v.x, v.y);
        p.y = pack_h2(v.z, v.w);
        xh[i] = p;
    }
}

// ---------------- GEMM: C[NN, OUT] = A[NN,128] @ W[OUT,128]^T (+bias) ------
// Persistent multi-tile fp16 MMA GEMM with cp.async double-buffered A tiles.
// A is fp16 in global. W loaded+converted to smem ONCE per CTA.
// Block: 256 threads = 8 warps (4 m x 2 n). Block tile 128 x OUT.
// smem row stride: 68 half2-words (64 data + 4 pad) -> conflict-free LDS.
template <int OUT, bool HOUT>
__global__ void __launch_bounds__(256, 2) k_gemm(
    const __half* __restrict__ A, const float* __restrict__ W,
    const float* __restrict__ bias, void* __restrict__ Cv)
{
    constexpr int NA = OUT / 16;          // n-atoms per warp (8 or 4)
    constexpr int XWORDS = 128 * 68;
    extern __shared__ uint32_t sm[];      // half2 units
    uint32_t* Xstage[2] = { sm, sm + XWORDS };
    uint32_t* Ws = sm + 2 * XWORDS;       // [OUT][68]
    const int tid  = threadIdx.x;
    const int warp = tid >> 5;
    const int lane = tid & 31;

    const int m_off = (warp >> 1) * 32;        // 0,32,64,96
    const int n_off = (warp & 1) * (OUT / 2);  // 0, OUT/2
    const int gid = lane >> 2;                 // group id 0..7
    const int tig = lane & 3;                  // thread in group 0..3

    // A-tile async fill: 128 rows x 256B = 2048 x 16B chunks, 8 per thread
    auto fill_async = [&](uint32_t* Xs, int t) {
        int row0 = t * 128;
        #pragma unroll
        for (int i = 0; i < 8; i++) {
            int idx = tid + i * 256;
            int r = idx >> 4, c8 = idx & 15;
            uint32_t dst = (uint32_t)__cvta_generic_to_shared(&Xs[r * 68 + c8 * 4]);
            const void* src = (const char*)A + ((size_t)(row0 + r) * 128 + c8 * 8) * 2;
            int sz = (row0 + r < NN) ? 16 : 0;
            asm volatile("cp.async.cg.shared.global [%0], [%1], 16, %2;"
                         :: "r"(dst), "l"(src), "r"(sz));
        }
        asm volatile("cp.async.commit_group;");
    };

    int tile = blockIdx.x;
    if (tile < NTILES) fill_async(Xstage[0], tile);

    // W tile load + convert (once per CTA), overlapped with tile0 cp.async
    for (int idx = tid; idx < OUT * 32; idx += 256) {
        int j = idx >> 5, c4 = idx & 31;
        float4 v = reinterpret_cast<const float4*>(W)[idx];
        uint2 p;
        p.x = pack_h2(v.x, v.y);
        p.y = pack_h2(v.z, v.w);
        *reinterpret_cast<uint2*>(&Ws[j * 68 + c4 * 2]) = p;
    }

    int stage = 0;
    for (; tile < NTILES; tile += GEMM_GRID) {
        int next = tile + GEMM_GRID;
        if (next < NTILES) {
            fill_async(Xstage[stage ^ 1], next);
            asm volatile("cp.async.wait_group 1;");
        } else {
            asm volatile("cp.async.wait_group 0;");
        }
        __syncthreads();
        const uint32_t* Xs = Xstage[stage];
        const int row0 = tile * 128;

        float acc[2][NA][4];
        #pragma unroll
        for (int ma = 0; ma < 2; ma++)
            #pragma unroll
            for (int na = 0; na < NA; na++)
                #pragma unroll
                for (int c = 0; c < 4; c++) acc[ma][na][c] = 0.f;

        #pragma unroll
        for (int ks = 0; ks < 8; ks++) {           // k0 = ks*16
            uint32_t a[2][4];
            #pragma unroll
            for (int ma = 0; ma < 2; ma++) {
                int row = m_off + ma * 16 + gid;
                a[ma][0] = Xs[row * 68 + ks * 8 + tig];
                a[ma][1] = Xs[(row + 8) * 68 + ks * 8 + tig];
                a[ma][2] = Xs[row * 68 + ks * 8 + tig + 4];
                a[ma][3] = Xs[(row + 8) * 68 + ks * 8 + tig + 4];
            }
            #pragma unroll
            for (int na = 0; na < NA; na++) {
                int n = n_off + na * 8 + gid;
                uint32_t b0 = Ws[n * 68 + ks * 8 + tig];
                uint32_t b1 = Ws[n * 68 + ks * 8 + tig + 4];
                #pragma unroll
                for (int ma = 0; ma < 2; ma++) {
                    float* d = acc[ma][na];
                    mma_f16(d[0], d[1], d[2], d[3],
                            a[ma][0], a[ma][1], a[ma][2], a[ma][3], b0, b1);
                }
            }
        }

        // epilogue
        #pragma unroll
        for (int ma = 0; ma < 2; ma++) {
            #pragma unroll
            for (int na = 0; na < NA; na++) {
                int col = n_off + na * 8 + 2 * tig;
                float bx = 0.f, by = 0.f;
                if (bias) { bx = __ldg(&bias[col]); by = __ldg(&bias[col + 1]); }
                int r0 = row0 + m_off + ma * 16 + gid;
                int r1 = r0 + 8;
                if (HOUT) {
                    __half* C = (__half*)Cv;
                    if (r0 < NN)
                        *reinterpret_cast<__half2*>(&C[(size_t)r0 * OUT + col]) =
                            __floats2half2_rn(acc[ma][na][0] + bx, acc[ma][na][1] + by);
                    if (r1 < NN)
                        *reinterpret_cast<__half2*>(&C[(size_t)r1 * OUT + col]) =
                            __floats2half2_rn(acc[ma][na][2] + bx, acc[ma][na][3] + by);
                } else {
                    float* C = (float*)Cv;
                    if (r0 < NN)
                        *reinterpret_cast<float2*>(&C[(size_t)r0 * OUT + col]) =
                            make_float2(acc[ma][na][0] + bx, acc[ma][na][1] + by);
                    if (r1 < NN)
                        *reinterpret_cast<float2*>(&C[(size_t)r1 * OUT + col]) =
                            make_float2(acc[ma][na][2] + bx, acc[ma][na][3] + by);
                }
            }
        }
        __syncthreads();
        stage ^= 1;
    }
}

// -------- aggregation + self-loop + bias + ReLU fused: warp per node -------
// Warp batch-loads 32 (src, norm) pairs in one vector LDG, shfl-broadcasts,
// inner loop unrolled x8 (8 row-gathers in flight).
__global__ void k_agg_relu(const __half* __restrict__ h,
                           const float* __restrict__ bias,
                           __half* __restrict__ out)
{
    int gw = (blockIdx.x * blockDim.x + threadIdx.x) >> 5;   // node id
    if (gw >= NN) return;
    int lane = threadIdx.x & 31;
    int beg = g_rowstart[gw];
    int cnt = g_deg[gw];
    const uint2* hp = reinterpret_cast<const uint2*>(h);

    float4 acc[4];
    #pragma unroll
    for (int q = 0; q < 4; q++) acc[q] = make_float4(0.f, 0.f, 0.f, 0.f);

    for (int t0 = 0; t0 < cnt; t0 += 32) {
        int2 pr = make_int2(0, 0);
        if (t0 + lane < cnt) pr = __ldg(&g_pair[beg + t0 + lane]);
        int m = min(32, cnt - t0);
        int j = 0;
        for (; j + 8 <= m; j += 8) {
            int ss[8]; float nn[8]; uint2 uu[8];
            #pragma unroll
            for (int q = 0; q < 8; q++) {
                ss[q] = __shfl_sync(0xFFFFFFFFu, pr.x, j + q);
                nn[q] = __int_as_float(__shfl_sync(0xFFFFFFFFu, pr.y, j + q));
            }
            #pragma unroll
            for (int q = 0; q < 8; q++)
                uu[q] = __ldg(&hp[(size_t)ss[q] * 32 + lane]);
            #pragma unroll
            for (int q = 0; q < 8; q++) {
                float2 pa = __half22float2(*reinterpret_cast<__half2*>(&uu[q].x));
                float2 pb = __half22float2(*reinterpret_cast<__half2*>(&uu[q].y));
                float4& a = acc[q & 3];
                a.x += nn[q] * pa.x; a.y += nn[q] * pa.y;
                a.z += nn[q] * pb.x; a.w += nn[q] * pb.y;
            }
        }
        for (; j < m; j++) {
            int   s0 = __shfl_sync(0xFFFFFFFFu, pr.x, j);
            float n0 = __int_as_float(__shfl_sync(0xFFFFFFFFu, pr.y, j));
            uint2 u0 = __ldg(&hp[(size_t)s0 * 32 + lane]);
            float2 pa = __half22float2(*reinterpret_cast<__half2*>(&u0.x));
            float2 pb = __half22float2(*reinterpret_cast<__half2*>(&u0.y));
            acc[0].x += n0 * pa.x; acc[0].y += n0 * pa.y;
            acc[0].z += n0 * pb.x; acc[0].w += n0 * pb.y;
        }
    }

    float dinv_d = g_dinv[gw];
    float c = dinv_d * dinv_d;                          // self-loop norm
    uint2 us = __ldg(&hp[(size_t)gw * 32 + lane]);
    float2 sa = __half22float2(*reinterpret_cast<__half2*>(&us.x));
    float2 sb = __half22float2(*reinterpret_cast<__half2*>(&us.y));
    float4 b  = __ldg(&reinterpret_cast<const float4*>(bias)[lane]);
    float rx = fmaxf(acc[0].x + acc[1].x + acc[2].x + acc[3].x + c * sa.x + b.x, 0.f);
    float ry = fmaxf(acc[0].y + acc[1].y + acc[2].y + acc[3].y + c * sa.y + b.y, 0.f);
    float rz = fmaxf(acc[0].z + acc[1].z + acc[2].z + acc[3].z + c * sb.x + b.z, 0.f);
    float rw = fmaxf(acc[0].w + acc[1].w + acc[2].w + acc[3].w + c * sb.y + b.w, 0.f);
    uint2 o;
    o.x = pack_h2(rx, ry);
    o.y = pack_h2(rz, rw);
    reinterpret_cast<uint2*>(out)[(size_t)gw * 32 + lane] = o;
}

// ---------------- launcher --------------------------------------------------
extern "C" void kernel_launch(void* const* d_in, const int* in_sizes, int n_in,
                              void* d_out, int out_size)
{
    (void)in_sizes; (void)n_in; (void)out_size;
    const float* x  = (const float*)d_in[0];
    const int*   ei = (const int*)d_in[1];          // int32 (JAX x64 disabled)
    const float* W1 = (const float*)d_in[2];
    const float* b1 = (const float*)d_in[3];
    const float* W2 = (const float*)d_in[4];
    const float* b2 = (const float*)d_in[5];
    const float* Wl = (const float*)d_in[6];
    const float* bl = (const float*)d_in[7];
    float* out = (float*)d_out;

    void *pxh, *pbh, *pba, *pdeg, *pcur, *pst;
    cudaGetSymbolAddress(&pxh, g_xh);
    cudaGetSymbolAddress(&pbh, g_bufh);
    cudaGetSymbolAddress(&pba, g_bufact);
    cudaGetSymbolAddress(&pdeg, g_deg);
    cudaGetSymbolAddress(&pcur, g_cursor);
    cudaGetSymbolAddress(&pst,  g_status);
    __half* xh = (__half*)pxh;
    __half* bufh = (__half*)pbh;
    __half* bufact = (__half*)pba;

    const int SMEM128 = (2 * 128 * 68 + 128 * 68) * 4;   // 104448 B
    const int SMEM64  = (2 * 128 * 68 + 64 * 68) * 4;    // 87040 B
    cudaFuncSetAttribute((const void*)k_gemm<128, true>,
                         cudaFuncAttributeMaxDynamicSharedMemorySize, SMEM128);
    cudaFuncSetAttribute((const void*)k_gemm<64, false>,
                         cudaFuncAttributeMaxDynamicSharedMemorySize, SMEM64);

    const int TB = 256;
    const int GB_E  = (NE + TB - 1) / TB;          // 6250
    const int GB_W  = (NN * 32 + TB - 1) / TB;     // 12500 (warp per node)

    // --- zero-init via memset nodes (not kernel launches) ---
    cudaMemsetAsync(pdeg, 0, NN * sizeof(int));
    cudaMemsetAsync(pcur, 0, NN * sizeof(int));
    cudaMemsetAsync(pst,  0, NB_SCAN * sizeof(int));

    // --- graph preprocessing ---
    k_count<<<GB_E, TB>>>(ei);
    k_scan<<<NB_SCAN, 1024>>>();
    k_fill<<<GB_E, TB>>>(ei);
    k_cvt<<<GB_W, TB>>>((const float4*)x, (uint2*)xh);

    // --- layer 1 ---
    k_gemm<128, true><<<GEMM_GRID, TB, SMEM128>>>(xh, W1, nullptr, bufh);
    k_agg_relu<<<GB_W, TB>>>(bufh, b1, bufact);

    // --- layer 2 ---
    k_gemm<128, true><<<GEMM_GRID, TB, SMEM128>>>(bufact, W2, nullptr, bufh);
    k_agg_relu<<<GB_W, TB>>>(bufh, b2, bufact);

    // --- readout ---
    k_gemm<64, false><<<GEMM_GRID, TB, SMEM64>>>(bufact, Wl, bl, out);
}

// round 11
// speedup vs baseline: 1.7182x; 1.0005x over previous
#include <cuda_runtime.h>
#include <cuda_fp16.h>
#include <cstdint>

// Problem constants (fixed by the dataset)
#define NN   100000       // nodes
#define NE   1600000      // edges (excluding self loops)
#define FD   128          // feature / hidden dim
#define NC   64           // classes
#define NB_SCAN 98        // ceil(NN / 1024), all blocks co-resident (<148 SMs)
#define NTILES 782        // ceil(NN / 128)
#define GEMM_GRID 296     // 2 CTAs/SM * 148 SMs

// ---------------- scratch (device globals; no allocation allowed) ----------
__device__ __half g_xh[NN * FD];     // x converted to fp16 (GEMM-1 input)
__device__ __half g_bufh[NN * FD];   // GEMM output h (fp16, gather operand)
__device__ __half g_bufact[NN * FD]; // agg+relu output (fp16, GEMM input)
__device__ float  g_dinv[NN];
__device__ int    g_deg[NN];         // in-degree (without self loop)
__device__ int    g_rowstart[NN];    // exclusive prefix of deg
__device__ int    g_cursor[NN];
__device__ int2   g_pair[NE];        // (src, norm-bits) per edge, grouped by dst
__device__ int    g_status[NB_SCAN]; // lookback scan status (memset to 0)

__device__ __forceinline__ uint32_t pack_h2(float x, float y)
{
    __half2 h = __floats2half2_rn(x, y);
    return *reinterpret_cast<uint32_t*>(&h);
}

// ---------------- preprocessing kernels ------------------------------------

// Fused: degree count (threads < NE) + x -> fp16 conversion (all 3.2M threads).
// grid = 12500 x 256 = 3,200,000 = NN*32 exactly.
__global__ void k_count_cvt(const int* __restrict__ ei,
                            const float4* __restrict__ x,
                            uint2* __restrict__ xh)
{
    int i = blockIdx.x * blockDim.x + threadIdx.x;
    if (i < NE) {
        int d = ei[NE + i];
        atomicAdd(&g_deg[d], 1);
    }
    // cvt: i in [0, NN*32)
    float4 v = __ldg(&x[i]);
    uint2 p;
    p.x = pack_h2(v.x, v.y);
    p.y = pack_h2(v.z, v.w);
    xh[i] = p;
}

// Single-pass scan over g_deg -> g_rowstart (exclusive), plus dinv.
// 98 blocks of 1024 threads, all resident simultaneously -> lookback is safe.
__global__ void __launch_bounds__(1024) k_scan()
{
    __shared__ int s[1024];
    __shared__ int sh_prefix;
    int t = threadIdx.x;
    int i = blockIdx.x * 1024 + t;
    int v = (i < NN) ? g_deg[i] : 0;
    s[t] = v;
    __syncthreads();
    #pragma unroll
    for (int off = 1; off < 1024; off <<= 1) {
        int add = (t >= off) ? s[t - off] : 0;
        __syncthreads();
        s[t] += add;
        __syncthreads();
    }
    if (t == 1023) {
        int total = s[t];                       // < 2^30 always
        __threadfence();
        atomicExch(&g_status[blockIdx.x], total | 0x40000000);
    }
    if (t == 0) {
        int p = 0;
        for (int j = 0; j < (int)blockIdx.x; j++) {
            int st;
            do { st = atomicAdd(&g_status[j], 0); } while (!(st & 0x40000000));
            p += st & 0x3FFFFFFF;
        }
        sh_prefix = p;
    }
    __syncthreads();
    if (i < NN) {
        g_rowstart[i] = s[t] - v + sh_prefix;
        g_dinv[i] = rsqrtf((float)v + 1.0f);    // +1 = self loop
    }
}

__global__ void k_fill(const int* __restrict__ ei)
{
    int e = blockIdx.x * blockDim.x + threadIdx.x;
    if (e < NE) {
        int s = ei[e];
        int d = ei[NE + e];
        int p = g_rowstart[d] + atomicAdd(&g_cursor[d], 1);
        float nm = __ldg(&g_dinv[s]) * __ldg(&g_dinv[d]);
        g_pair[p] = make_int2(s, __float_as_int(nm));
    }
}

// ---------------- fp16 MMA helper ------------------------------------------
__device__ __forceinline__ void mma_f16(
    float& d0, float& d1, float& d2, float& d3,
    uint32_t a0, uint32_t a1, uint32_t a2, uint32_t a3,
    uint32_t b0, uint32_t b1)
{
    asm volatile(
        "mma.sync.aligned.m16n8k16.row.col.f32.f16.f16.f32 "
        "{%0,%1,%2,%3}, {%4,%5,%6,%7}, {%8,%9}, {%0,%1,%2,%3};"
        : "+f"(d0), "+f"(d1), "+f"(d2), "+f"(d3)
        : "r"(a0), "r"(a1), "r"(a2), "r"(a3), "r"(b0), "r"(b1));
}

// ---------------- GEMM: C[NN, OUT] = A[NN,128] @ W[OUT,128]^T (+bias) ------
// Persistent multi-tile fp16 MMA GEMM with cp.async double-buffered A tiles.
// A is fp16 in global. W loaded+converted to smem ONCE per CTA.
// Block: 256 threads = 8 warps (4 m x 2 n). Block tile 128 x OUT.
// smem row stride: 68 half2-words (64 data + 4 pad) -> conflict-free LDS.
template <int OUT, bool HOUT>
__global__ void __launch_bounds__(256, 2) k_gemm(
    const __half* __restrict__ A, const float* __restrict__ W,
    const float* __restrict__ bias, void* __restrict__ Cv)
{
    constexpr int NA = OUT / 16;          // n-atoms per warp (8 or 4)
    constexpr int XWORDS = 128 * 68;
    extern __shared__ uint32_t sm[];      // half2 units
    uint32_t* Xstage[2] = { sm, sm + XWORDS };
    uint32_t* Ws = sm + 2 * XWORDS;       // [OUT][68]
    const int tid  = threadIdx.x;
    const int warp = tid >> 5;
    const int lane = tid & 31;

    const int m_off = (warp >> 1) * 32;        // 0,32,64,96
    const int n_off = (warp & 1) * (OUT / 2);  // 0, OUT/2
    const int gid = lane >> 2;                 // group id 0..7
    const int tig = lane & 3;                  // thread in group 0..3

    // A-tile async fill: 128 rows x 256B = 2048 x 16B chunks, 8 per thread
    auto fill_async = [&](uint32_t* Xs, int t) {
        int row0 = t * 128;
        #pragma unroll
        for (int i = 0; i < 8; i++) {
            int idx = tid + i * 256;
            int r = idx >> 4, c8 = idx & 15;
            uint32_t dst = (uint32_t)__cvta_generic_to_shared(&Xs[r * 68 + c8 * 4]);
            const void* src = (const char*)A + ((size_t)(row0 + r) * 128 + c8 * 8) * 2;
            int sz = (row0 + r < NN) ? 16 : 0;
            asm volatile("cp.async.cg.shared.global [%0], [%1], 16, %2;"
                         :: "r"(dst), "l"(src), "r"(sz));
        }
        asm volatile("cp.async.commit_group;");
    };

    int tile = blockIdx.x;
    if (tile < NTILES) fill_async(Xstage[0], tile);

    // W tile load + convert (once per CTA), overlapped with tile0 cp.async
    for (int idx = tid; idx < OUT * 32; idx += 256) {
        int j = idx >> 5, c4 = idx & 31;
        float4 v = reinterpret_cast<const float4*>(W)[idx];
        uint2 p;
        p.x = pack_h2(v.x, v.y);
        p.y = pack_h2(v.z, v.w);
        *reinterpret_cast<uint2*>(&Ws[j * 68 + c4 * 2]) = p;
    }

    int stage = 0;
    for (; tile < NTILES; tile += GEMM_GRID) {
        int next = tile + GEMM_GRID;
        if (next < NTILES) {
            fill_async(Xstage[stage ^ 1], next);
            asm volatile("cp.async.wait_group 1;");
        } else {
            asm volatile("cp.async.wait_group 0;");
        }
        __syncthreads();
        const uint32_t* Xs = Xstage[stage];
        const int row0 = tile * 128;

        float acc[2][NA][4];
        #pragma unroll
        for (int ma = 0; ma < 2; ma++)
            #pragma unroll
            for (int na = 0; na < NA; na++)
                #pragma unroll
                for (int c = 0; c < 4; c++) acc[ma][na][c] = 0.f;

        #pragma unroll
        for (int ks = 0; ks < 8; ks++) {           // k0 = ks*16
            uint32_t a[2][4];
            #pragma unroll
            for (int ma = 0; ma < 2; ma++) {
                int row = m_off + ma * 16 + gid;
                a[ma][0] = Xs[row * 68 + ks * 8 + tig];
                a[ma][1] = Xs[(row + 8) * 68 + ks * 8 + tig];
                a[ma][2] = Xs[row * 68 + ks * 8 + tig + 4];
                a[ma][3] = Xs[(row + 8) * 68 + ks * 8 + tig + 4];
            }
            #pragma unroll
            for (int na = 0; na < NA; na++) {
                int n = n_off + na * 8 + gid;
                uint32_t b0 = Ws[n * 68 + ks * 8 + tig];
                uint32_t b1 = Ws[n * 68 + ks * 8 + tig + 4];
                #pragma unroll
                for (int ma = 0; ma < 2; ma++) {
                    float* d = acc[ma][na];
                    mma_f16(d[0], d[1], d[2], d[3],
                            a[ma][0], a[ma][1], a[ma][2], a[ma][3], b0, b1);
                }
            }
        }

        // epilogue
        #pragma unroll
        for (int ma = 0; ma < 2; ma++) {
            #pragma unroll
            for (int na = 0; na < NA; na++) {
                int col = n_off + na * 8 + 2 * tig;
                float bx = 0.f, by = 0.f;
                if (bias) { bx = __ldg(&bias[col]); by = __ldg(&bias[col + 1]); }
                int r0 = row0 + m_off + ma * 16 + gid;
                int r1 = r0 + 8;
                if (HOUT) {
                    __half* C = (__half*)Cv;
                    if (r0 < NN)
                        *reinterpret_cast<__half2*>(&C[(size_t)r0 * OUT + col]) =
                            __floats2half2_rn(acc[ma][na][0] + bx, acc[ma][na][1] + by);
                    if (r1 < NN)
                        *reinterpret_cast<__half2*>(&C[(size_t)r1 * OUT + col]) =
                            __floats2half2_rn(acc[ma][na][2] + bx, acc[ma][na][3] + by);
                } else {
                    float* C = (float*)Cv;
                    if (r0 < NN)
                        *reinterpret_cast<float2*>(&C[(size_t)r0 * OUT + col]) =
                            make_float2(acc[ma][na][0] + bx, acc[ma][na][1] + by);
                    if (r1 < NN)
                        *reinterpret_cast<float2*>(&C[(size_t)r1 * OUT + col]) =
                            make_float2(acc[ma][na][2] + bx, acc[ma][na][3] + by);
                }
            }
        }
        __syncthreads();
        stage ^= 1;
    }
}

// -------- aggregation + self-loop + bias + ReLU fused: warp per node -------
// Warp batch-loads 32 (src, norm) pairs (double-buffered across batches),
// shfl-broadcasts, inner loop unrolled x8 (8 row-gathers in flight).
__global__ void k_agg_relu(const __half* __restrict__ h,
                           const float* __restrict__ bias,
                           __half* __restrict__ out)
{
    int gw = (blockIdx.x * blockDim.x + threadIdx.x) >> 5;   // node id
    if (gw >= NN) return;
    int lane = threadIdx.x & 31;
    int beg = g_rowstart[gw];
    int cnt = g_deg[gw];
    const uint2* hp = reinterpret_cast<const uint2*>(h);

    float4 acc[4];
    #pragma unroll
    for (int q = 0; q < 4; q++) acc[q] = make_float4(0.f, 0.f, 0.f, 0.f);

    // prefetch batch 0
    int2 pr = make_int2(0, 0);
    if (lane < cnt) pr = __ldg(&g_pair[beg + lane]);

    for (int t0 = 0; t0 < cnt; t0 += 32) {
        // prefetch next batch before consuming current
        int2 pr_next = make_int2(0, 0);
        int tn = t0 + 32 + lane;
        if (tn < cnt) pr_next = __ldg(&g_pair[beg + tn]);

        int m = min(32, cnt - t0);
        int j = 0;
        for (; j + 8 <= m; j += 8) {
            int ss[8]; float nn[8]; uint2 uu[8];
            #pragma unroll
            for (int q = 0; q < 8; q++) {
                ss[q] = __shfl_sync(0xFFFFFFFFu, pr.x, j + q);
                nn[q] = __int_as_float(__shfl_sync(0xFFFFFFFFu, pr.y, j + q));
            }
            #pragma unroll
            for (int q = 0; q < 8; q++)
                uu[q] = __ldg(&hp[(size_t)ss[q] * 32 + lane]);
            #pragma unroll
            for (int q = 0; q < 8; q++) {
                float2 pa = __half22float2(*reinterpret_cast<__half2*>(&uu[q].x));
                float2 pb = __half22float2(*reinterpret_cast<__half2*>(&uu[q].y));
                float4& a = acc[q & 3];
                a.x += nn[q] * pa.x; a.y += nn[q] * pa.y;
                a.z += nn[q] * pb.x; a.w += nn[q] * pb.y;
            }
        }
        for (; j < m; j++) {
            int   s0 = __shfl_sync(0xFFFFFFFFu, pr.x, j);
            float n0 = __int_as_float(__shfl_sync(0xFFFFFFFFu, pr.y, j));
            uint2 u0 = __ldg(&hp[(size_t)s0 * 32 + lane]);
            float2 pa = __half22float2(*reinterpret_cast<__half2*>(&u0.x));
            float2 pb = __half22float2(*reinterpret_cast<__half2*>(&u0.y));
            acc[0].x += n0 * pa.x; acc[0].y += n0 * pa.y;
            acc[0].z += n0 * pb.x; acc[0].w += n0 * pb.y;
        }
        pr = pr_next;
    }

    float dinv_d = g_dinv[gw];
    float c = dinv_d * dinv_d;                          // self-loop norm
    uint2 us = __ldg(&hp[(size_t)gw * 32 + lane]);
    float2 sa = __half22float2(*reinterpret_cast<__half2*>(&us.x));
    float2 sb = __half22float2(*reinterpret_cast<__half2*>(&us.y));
    float4 b  = __ldg(&reinterpret_cast<const float4*>(bias)[lane]);
    float rx = fmaxf(acc[0].x + acc[1].x + acc[2].x + acc[3].x + c * sa.x + b.x, 0.f);
    float ry = fmaxf(acc[0].y + acc[1].y + acc[2].y + acc[3].y + c * sa.y + b.y, 0.f);
    float rz = fmaxf(acc[0].z + acc[1].z + acc[2].z + acc[3].z + c * sb.x + b.z, 0.f);
    float rw = fmaxf(acc[0].w + acc[1].w + acc[2].w + acc[3].w + c * sb.y + b.w, 0.f);
    uint2 o;
    o.x = pack_h2(rx, ry);
    o.y = pack_h2(rz, rw);
    reinterpret_cast<uint2*>(out)[(size_t)gw * 32 + lane] = o;
}

// ---------------- launcher --------------------------------------------------
extern "C" void kernel_launch(void* const* d_in, const int* in_sizes, int n_in,
                              void* d_out, int out_size)
{
    (void)in_sizes; (void)n_in; (void)out_size;
    const float* x  = (const float*)d_in[0];
    const int*   ei = (const int*)d_in[1];          // int32 (JAX x64 disabled)
    const float* W1 = (const float*)d_in[2];
    const float* b1 = (const float*)d_in[3];
    const float* W2 = (const float*)d_in[4];
    const float* b2 = (const float*)d_in[5];
    const float* Wl = (const float*)d_in[6];
    const float* bl = (const float*)d_in[7];
    float* out = (float*)d_out;

    void *pxh, *pbh, *pba, *pdeg, *pcur, *pst;
    cudaGetSymbolAddress(&pxh, g_xh);
    cudaGetSymbolAddress(&pbh, g_bufh);
    cudaGetSymbolAddress(&pba, g_bufact);
    cudaGetSymbolAddress(&pdeg, g_deg);
    cudaGetSymbolAddress(&pcur, g_cursor);
    cudaGetSymbolAddress(&pst,  g_status);
    __half* xh = (__half*)pxh;
    __half* bufh = (__half*)pbh;
    __half* bufact = (__half*)pba;

    const int SMEM128 = (2 * 128 * 68 + 128 * 68) * 4;   // 104448 B
    const int SMEM64  = (2 * 128 * 68 + 64 * 68) * 4;    // 87040 B
    cudaFuncSetAttribute((const void*)k_gemm<128, true>,
                         cudaFuncAttributeMaxDynamicSharedMemorySize, SMEM128);
    cudaFuncSetAttribute((const void*)k_gemm<64, false>,
                         cudaFuncAttributeMaxDynamicSharedMemorySize, SMEM64);

    const int TB = 256;
    const int GB_E  = (NE + TB - 1) / TB;          // 6250
    const int GB_W  = (NN * 32 + TB - 1) / TB;     // 12500 (warp per node)

    // --- zero-init via memset nodes (not kernel launches) ---
    cudaMemsetAsync(pdeg, 0, NN * sizeof(int));
    cudaMemsetAsync(pcur, 0, NN * sizeof(int));
    cudaMemsetAsync(pst,  0, NB_SCAN * sizeof(int));

    // --- graph preprocessing (fused count+cvt, scan, fill) ---
    k_count_cvt<<<GB_W, TB>>>(ei, (const float4*)x, (uint2*)xh);
    k_scan<<<NB_SCAN, 1024>>>();
    k_fill<<<GB_E, TB>>>(ei);

    // --- layer 1 ---
    k_gemm<128, true><<<GEMM_GRID, TB, SMEM128>>>(xh, W1, nullptr, bufh);
    k_agg_relu<<<GB_W, TB>>>(bufh, b1, bufact);

    // --- layer 2 ---
    k_gemm<128, true><<<GEMM_GRID, TB, SMEM128>>>(bufact, W2, nullptr, bufh);
    k_agg_relu<<<GB_W, TB>>>(bufh, b2, bufact);

    // --- readout ---
    k_gemm<64, false><<<GEMM_GRID, TB, SMEM64>>>(bufact, Wl, bl, out);
}